// round 11
// baseline (speedup 1.0000x reference)
#include <cuda_runtime.h>

#define FULL_MASK 0xffffffffu

constexpr int L          = 32;
constexpr int THREADS    = 128;    // 4 warps
constexpr int GRID       = 4096;
constexpr int T          = 2;      // 4-row tiles per pipeline stage
constexpr int MAX_BLOCKS = 65536;

__device__ float        g_partial[MAX_BLOCKS];
__device__ unsigned int g_ticket = 0;

// Per 4-row tile t: lane l serves row (4t + (l>>3)), float4 column (l&7).
// Global float4 index = t*32 + lane -> one LDG.128 per warp = 512B coalesced.
//
// per_row = S^2 - (2/31) * (S * sum_{m<31} P_m - sum_{m<31} P_m^2)
// Linear in per-lane partials sp, sp2 -> each lane accumulates its own share.
__device__ __forceinline__ float tile_contrib(float4 x, float4 d, int sub, bool valid)
{
    float e0 = __expf(x.x), e1 = __expf(x.y), e2 = __expf(x.z), e3 = __expf(x.w);
    float den = (e0 + e1) + (e2 + e3);
    den += __shfl_xor_sync(FULL_MASK, den, 1);
    den += __shfl_xor_sync(FULL_MASK, den, 2);
    den += __shfl_xor_sync(FULL_MASK, den, 4);
    const float inv = __fdividef(1.0f, den);

    float q0 = fmaf(-e0, inv, d.x);
    float q1 = fmaf(-e1, inv, d.y);
    float q2 = fmaf(-e2, inv, d.z);
    float q3 = fmaf(-e3, inv, d.w);
    float p0 = q0, p1 = p0 + q1, p2 = p1 + q2, p3 = p2 + q3;

    // segmented inclusive scan of lane sums across the 8 sublanes
    float v = p3, t;
    t = __shfl_up_sync(FULL_MASK, v, 1); if (sub >= 1) v += t;
    t = __shfl_up_sync(FULL_MASK, v, 2); if (sub >= 2) v += t;
    t = __shfl_up_sync(FULL_MASK, v, 4); if (sub >= 4) v += t;
    const float excl = v - p3;

    float P0 = excl + p0, P1 = excl + p1, P2 = excl + p2, P3 = excl + p3;

    // lane partials over m < 31 (sublane 7 excludes P_31)
    float sp, sp2;
    if (sub == 7) {
        sp  = (P0 + P1) + P2;
        sp2 = fmaf(P0, P0, fmaf(P1, P1, P2 * P2));
    } else {
        sp  = (P0 + P1) + (P2 + P3);
        sp2 = fmaf(P0, P0, fmaf(P1, P1, fmaf(P2, P2, P3 * P3)));
    }

    const float S = __shfl_sync(FULL_MASK, v, (threadIdx.x & 31) | 7);

    float c = (2.0f / 31.0f) * fmaf(-S, sp, sp2);
    if (sub == 0) c = fmaf(S, S, c);
    return valid ? c : 0.f;
}

struct Buf { float4 x[T], d[T]; };

__device__ __forceinline__ void load_buf(Buf& b, unsigned t0, unsigned lane,
                                         unsigned maxf4,
                                         const float4* __restrict__ gL,
                                         const float4* __restrict__ gD)
{
    #pragma unroll
    for (int k = 0; k < T; ++k) {
        unsigned idx = (t0 + k) * 32u + lane;
        if (idx > maxf4) idx = maxf4;     // clamp: safe unconditional prefetch
        b.x[k] = __ldg(&gL[idx]);
        b.d[k] = __ldg(&gD[idx]);
    }
}

__device__ __forceinline__ void compute_buf(const Buf& b, unsigned t0, int sub,
                                            int grp, unsigned B, float& acc)
{
    #pragma unroll
    for (int k = 0; k < T; ++k) {
        bool valid = (t0 + k) * 4u + grp < B;
        acc += tile_contrib(b.x[k], b.d[k], sub, valid);
    }
}

__global__ __launch_bounds__(THREADS)
void qfd2_warp_kernel(const float* __restrict__ logits,
                      const float* __restrict__ D,
                      int B, float* __restrict__ out)
{
    __shared__ float wsum[THREADS / 32];
    __shared__ int   sIsLast;

    const int tid  = threadIdx.x;
    const int lane = tid & 31;
    const int sub  = lane & 7;
    const int grp  = lane >> 3;

    const float4* gL = (const float4*)logits;
    const float4* gD = (const float4*)D;

    const unsigned ntiles = (unsigned)((B + 3) / 4);
    const unsigned nwarps = (unsigned)GRID * (THREADS / 32);
    const unsigned gw     = ((unsigned)blockIdx.x * THREADS + tid) >> 5;
    const unsigned stride = nwarps * T;
    const unsigned maxf4  = (unsigned)B * (L / 4) - 1;
    const unsigned t0     = gw * T;

    // gw*T < stride, so iteration count is UNIFORM across all warps.
    const unsigned niter = (ntiles + stride - 1) / stride;

    float acc = 0.f;

    Buf A, Bb;
    load_buf(A, t0, lane, maxf4, gL, gD);

    unsigned i = 0;
    for (; i + 2 <= niter; i += 2) {
        load_buf(Bb, t0 + (i + 1) * stride, lane, maxf4, gL, gD);  // prefetch
        compute_buf(A, t0 + i * stride, sub, grp, (unsigned)B, acc);
        load_buf(A, t0 + (i + 2) * stride, lane, maxf4, gL, gD);   // prefetch (clamped past end: safe)
        compute_buf(Bb, t0 + (i + 1) * stride, sub, grp, (unsigned)B, acc);
    }
    if (i < niter)
        compute_buf(A, t0 + i * stride, sub, grp, (unsigned)B, acc);

    // ---- Deterministic block reduction ----
    #pragma unroll
    for (int off = 16; off; off >>= 1)
        acc += __shfl_xor_sync(FULL_MASK, acc, off);

    const int wid = tid >> 5;
    if (lane == 0) wsum[wid] = acc;
    __syncthreads();

    const int nblocks = gridDim.x;
    if (tid == 0) {
        float b = 0.f;
        #pragma unroll
        for (int w = 0; w < THREADS / 32; ++w) b += wsum[w];
        g_partial[blockIdx.x] = b;
        __threadfence();
        unsigned int t = atomicAdd(&g_ticket, 1u);
        sIsLast = (t == (unsigned)(nblocks - 1));
    }
    __syncthreads();

    // ---- Last block reduces all partials (fixed order -> deterministic) ----
    if (sIsLast) {
        __threadfence();
        float s = 0.f;
        for (int j = tid; j < nblocks; j += THREADS)
            s += g_partial[j];

        #pragma unroll
        for (int off = 16; off; off >>= 1)
            s += __shfl_xor_sync(FULL_MASK, s, off);

        if (lane == 0) wsum[wid] = s;
        __syncthreads();
        if (tid == 0) {
            float total = 0.f;
            #pragma unroll
            for (int w = 0; w < THREADS / 32; ++w) total += wsum[w];
            out[0] = total / (float)B;
            g_ticket = 0;   // reset for next graph replay
        }
    }
}

extern "C" void kernel_launch(void* const* d_in, const int* in_sizes, int n_in,
                              void* d_out, int out_size)
{
    const float* logits = (const float*)d_in[0];   // D_pred_logit [B, 32]
    const float* D      = (const float*)d_in[1];   // D            [B, 32]
    float* out          = (float*)d_out;           // scalar f32

    const int B = in_sizes[0] / L;
    qfd2_warp_kernel<<<GRID, THREADS>>>(logits, D, B, out);
}

// round 12
// speedup vs baseline: 1.1278x; 1.1278x over previous
#include <cuda_runtime.h>
#include <cstdint>

#define FULL_MASK 0xffffffffu

constexpr int L            = 32;
constexpr int THREADS      = 128;      // 4 warps
constexpr int STAGES       = 3;
constexpr int ROWS_PER_STG = 64;       // 64 rows * 128B = 8KB per array per stage
constexpr int STG_BYTES    = ROWS_PER_STG * L * 4;       // 8192
constexpr int STG_TOTAL    = 2 * STG_BYTES;              // 16384 (L + D)
constexpr int SMEM_DYN     = STAGES * STG_TOTAL;         // 49152
constexpr int GRID         = 592;      // 4 blocks/SM * 148 SMs
constexpr int MAX_BLOCKS   = 65536;

__device__ float        g_partial[MAX_BLOCKS];
__device__ unsigned int g_ticket = 0;

__device__ __forceinline__ uint32_t smem_u32(const void* p) {
    uint32_t a;
    asm("{ .reg .u64 t; cvta.to.shared.u64 t, %1; cvt.u32.u64 %0, t; }" : "=r"(a) : "l"(p));
    return a;
}

__device__ __forceinline__ void mbar_init(uint32_t mbar, uint32_t count) {
    asm volatile("mbarrier.init.shared.b64 [%0], %1;" :: "r"(mbar), "r"(count) : "memory");
}
__device__ __forceinline__ void mbar_expect_tx(uint32_t mbar, uint32_t bytes) {
    asm volatile("mbarrier.arrive.expect_tx.shared.b64 _, [%0], %1;"
                 :: "r"(mbar), "r"(bytes) : "memory");
}
__device__ __forceinline__ void bulk_g2s(uint32_t dst, const void* src,
                                         uint32_t bytes, uint32_t mbar) {
    asm volatile("cp.async.bulk.shared::cta.global.mbarrier::complete_tx::bytes "
                 "[%0], [%1], %2, [%3];"
                 :: "r"(dst), "l"(src), "r"(bytes), "r"(mbar) : "memory");
}
__device__ __forceinline__ void mbar_wait(uint32_t mbar, uint32_t parity) {
    uint32_t done;
    asm volatile("{\n\t.reg .pred p;\n\t"
                 "mbarrier.try_wait.parity.acquire.cta.shared::cta.b64 p, [%1], %2;\n\t"
                 "selp.b32 %0, 1, 0, p;\n\t}"
                 : "=r"(done) : "r"(mbar), "r"(parity) : "memory");
    if (!done) {
        asm volatile("{\n\t.reg .pred P1;\n\t"
                     "W_%=:\n\t"
                     "mbarrier.try_wait.parity.acquire.cta.shared::cta.b64 P1, [%0], %1, 0x989680;\n\t"
                     "@P1 bra.uni D_%=;\n\t"
                     "bra.uni W_%=;\n\t"
                     "D_%=:\n\t}"
                     :: "r"(mbar), "r"(parity) : "memory");
    }
}

// Per 4-row tile: lane l serves row (l>>3), float4 column (l&7).
// per_row = S^2 - (2/31)*(S*sum_{m<31}P_m - sum_{m<31}P_m^2); linear in
// per-lane partials -> each lane accumulates its own share into acc.
__device__ __forceinline__ float tile_contrib(float4 x, float4 d, int sub, bool valid)
{
    float e0 = __expf(x.x), e1 = __expf(x.y), e2 = __expf(x.z), e3 = __expf(x.w);
    float den = (e0 + e1) + (e2 + e3);
    den += __shfl_xor_sync(FULL_MASK, den, 1);
    den += __shfl_xor_sync(FULL_MASK, den, 2);
    den += __shfl_xor_sync(FULL_MASK, den, 4);
    const float inv = __fdividef(1.0f, den);

    float q0 = fmaf(-e0, inv, d.x);
    float q1 = fmaf(-e1, inv, d.y);
    float q2 = fmaf(-e2, inv, d.z);
    float q3 = fmaf(-e3, inv, d.w);
    float p0 = q0, p1 = p0 + q1, p2 = p1 + q2, p3 = p2 + q3;

    float v = p3, t;
    t = __shfl_up_sync(FULL_MASK, v, 1); if (sub >= 1) v += t;
    t = __shfl_up_sync(FULL_MASK, v, 2); if (sub >= 2) v += t;
    t = __shfl_up_sync(FULL_MASK, v, 4); if (sub >= 4) v += t;
    const float excl = v - p3;

    float P0 = excl + p0, P1 = excl + p1, P2 = excl + p2, P3 = excl + p3;

    float sp, sp2;
    if (sub == 7) {   // holds P_28..P_31; exclude P_31
        sp  = (P0 + P1) + P2;
        sp2 = fmaf(P0, P0, fmaf(P1, P1, P2 * P2));
    } else {
        sp  = (P0 + P1) + (P2 + P3);
        sp2 = fmaf(P0, P0, fmaf(P1, P1, fmaf(P2, P2, P3 * P3)));
    }

    const float S = __shfl_sync(FULL_MASK, v, (threadIdx.x & 31) | 7);

    float c = (2.0f / 31.0f) * fmaf(-S, sp, sp2);
    if (sub == 0) c = fmaf(S, S, c);
    return valid ? c : 0.f;
}

__global__ __launch_bounds__(THREADS)
void qfd2_tma_kernel(const float* __restrict__ logits,
                     const float* __restrict__ D,
                     int B, float* __restrict__ out)
{
    extern __shared__ char dyn[];
    __shared__ __align__(8) unsigned long long mbar[STAGES];
    __shared__ float wsum[THREADS / 32];
    __shared__ int   sIsLast;

    const int tid  = threadIdx.x;
    const int lane = tid & 31;
    const int sub  = lane & 7;
    const int grp  = lane >> 3;
    const int wid  = tid >> 5;

    if (tid == 0) {
        #pragma unroll
        for (int s = 0; s < STAGES; ++s)
            mbar_init(smem_u32(&mbar[s]), 1);
    }
    __syncthreads();

    const unsigned bid = blockIdx.x;
    const unsigned G   = gridDim.x;
    const unsigned nst = ((unsigned)B + ROWS_PER_STG - 1) / ROWS_PER_STG;
    const unsigned niter = (nst > bid) ? (nst - bid + G - 1) / G : 0;

    auto issue = [&](unsigned i) {
        unsigned j     = bid + i * G;
        unsigned row0  = j * ROWS_PER_STG;
        unsigned rows  = (unsigned)B - row0;
        if (rows > ROWS_PER_STG) rows = ROWS_PER_STG;
        unsigned bytes = rows * (L * 4);
        int s = i % STAGES;
        uint32_t mb   = smem_u32(&mbar[s]);
        uint32_t dstL = smem_u32(dyn + s * STG_TOTAL);
        uint32_t dstD = dstL + STG_BYTES;
        mbar_expect_tx(mb, 2 * bytes);
        bulk_g2s(dstL, logits + (size_t)row0 * L, bytes, mb);
        bulk_g2s(dstD, D      + (size_t)row0 * L, bytes, mb);
    };

    // prologue: fill the pipeline
    if (tid == 0) {
        unsigned npro = niter < STAGES ? niter : STAGES;
        for (unsigned p = 0; p < npro; ++p) issue(p);
    }

    float acc = 0.f;

    for (unsigned i = 0; i < niter; ++i) {
        const int s = i % STAGES;
        const unsigned ph = (i / STAGES) & 1u;
        mbar_wait(smem_u32(&mbar[s]), ph);

        const float4* bL = (const float4*)(dyn + s * STG_TOTAL);
        const float4* bD = (const float4*)(dyn + s * STG_TOTAL + STG_BYTES);
        const unsigned row0 = (bid + i * G) * ROWS_PER_STG;

        #pragma unroll
        for (int k = 0; k < 4; ++k) {
            int t = wid * 4 + k;                       // tile within stage (0..15)
            float4 x = bL[t * 32 + lane];
            float4 d = bD[t * 32 + lane];
            bool valid = row0 + (unsigned)t * 4u + (unsigned)grp < (unsigned)B;
            acc += tile_contrib(x, d, sub, valid);
        }

        __syncthreads();                               // all done reading slot s
        if (tid == 0 && i + STAGES < niter) issue(i + STAGES);
    }

    // ---- Deterministic block reduction ----
    #pragma unroll
    for (int off = 16; off; off >>= 1)
        acc += __shfl_xor_sync(FULL_MASK, acc, off);

    if (lane == 0) wsum[wid] = acc;
    __syncthreads();

    const int nblocks = gridDim.x;
    if (tid == 0) {
        float b = 0.f;
        #pragma unroll
        for (int w = 0; w < THREADS / 32; ++w) b += wsum[w];
        g_partial[blockIdx.x] = b;
        __threadfence();
        unsigned int t = atomicAdd(&g_ticket, 1u);
        sIsLast = (t == (unsigned)(nblocks - 1));
    }
    __syncthreads();

    if (sIsLast) {
        __threadfence();
        float s = 0.f;
        for (int j = tid; j < nblocks; j += THREADS)
            s += g_partial[j];

        #pragma unroll
        for (int off = 16; off; off >>= 1)
            s += __shfl_xor_sync(FULL_MASK, s, off);

        if (lane == 0) wsum[wid] = s;
        __syncthreads();
        if (tid == 0) {
            float total = 0.f;
            #pragma unroll
            for (int w = 0; w < THREADS / 32; ++w) total += wsum[w];
            out[0] = total / (float)B;
            g_ticket = 0;   // reset for next graph replay
        }
    }
}

extern "C" void kernel_launch(void* const* d_in, const int* in_sizes, int n_in,
                              void* d_out, int out_size)
{
    const float* logits = (const float*)d_in[0];   // D_pred_logit [B, 32]
    const float* D      = (const float*)d_in[1];   // D            [B, 32]
    float* out          = (float*)d_out;           // scalar f32

    const int B = in_sizes[0] / L;

    static bool attr_set = false;
    if (!attr_set) {
        cudaFuncSetAttribute(qfd2_tma_kernel,
                             cudaFuncAttributeMaxDynamicSharedMemorySize, SMEM_DYN);
        attr_set = true;
    }
    qfd2_tma_kernel<<<GRID, THREADS, SMEM_DYN>>>(logits, D, B, out);
}